// round 5
// baseline (speedup 1.0000x reference)
#include <cuda_runtime.h>
#include <cstddef>

#define BATCH   8
#define T_LEN   4096
#define HC      256
#define HD      512
#define NROWS   (BATCH * T_LEN)
#define CHUNK   128
#define NCHUNK  (T_LEN / CHUNK)   // 32

__device__ float g_wx0[NROWS * HD];
__device__ float g_h0 [NROWS * HD];
__device__ float g_wx1[NROWS * HD];
// [0,64): layer0 progress per (b,rank) in chunks; [64,64+256): wx1 chunk ready
__device__ unsigned g_flags[64 + BATCH * NCHUNK];

// ---------------------------------------------------------------- helpers
static __device__ __forceinline__ unsigned su32(const void* p) {
    return (unsigned)__cvta_generic_to_shared(p);
}
static __device__ __forceinline__ unsigned long long packf2(float lo, float hi) {
    unsigned long long r;
    asm("mov.b64 %0, {%1, %2};" : "=l"(r) : "f"(lo), "f"(hi));
    return r;
}
static __device__ __forceinline__ void unpackf2(unsigned long long v, float& lo, float& hi) {
    asm("mov.b64 {%0, %1}, %2;" : "=f"(lo), "=f"(hi) : "l"(v));
}
static __device__ __forceinline__ float fast_tanh(float x) {
    float e = __expf(2.0f * x);
    return 1.0f - __fdividef(2.0f, e + 1.0f);
}
static __device__ __forceinline__ void mbar_wait(unsigned addr, unsigned parity) {
    asm volatile(
        "{\n\t.reg .pred P;\n"
        "LW_%=:\n\t"
        "mbarrier.try_wait.parity.acquire.cluster.shared::cta.b64 P, [%0], %1, 0x989680;\n\t"
        "@P bra LD_%=;\n\t"
        "bra LW_%=;\n"
        "LD_%=:\n\t}"
        :: "r"(addr), "r"(parity) : "memory");
}
static __device__ __forceinline__ unsigned ld_acq(const unsigned* p) {
    unsigned v;
    asm volatile("ld.acquire.gpu.global.u32 %0, [%1];" : "=r"(v) : "l"(p) : "memory");
    return v;
}
static __device__ __forceinline__ void st_rel(unsigned* p, unsigned v) {
    asm volatile("st.release.gpu.global.u32 [%0], %1;" :: "l"(p), "r"(v) : "memory");
}

// ---------------------------------------------------------------------------
// Projection GEMM (layer 0 only): Y[N,512] = X[N,512] @ Mw[512,512] + bias
// ---------------------------------------------------------------------------
__global__ __launch_bounds__(256) void proj_kernel(
    const float* __restrict__ X,
    const float* __restrict__ wr, const float* __restrict__ wi,
    const float* __restrict__ br, const float* __restrict__ bi,
    float* __restrict__ Y)
{
    __shared__ float As[16][132];
    __shared__ float Bs[16][132];

    const int bm  = blockIdx.x * 128;
    const int bn  = blockIdx.y * 128;
    const int tid = threadIdx.x;
    const int tx  = tid & 15;
    const int ty  = tid >> 4;

    const int am = tid >> 1;
    const int ak = (tid & 1) * 8;
    const int bk = tid >> 4;
    const int bj = (tid & 15) * 8;
    const bool jhi = (bn + bj) >= 256;
    const int  jj  = (bn + bj) & 255;

    float acc[8][8];
#pragma unroll
    for (int r = 0; r < 8; ++r)
#pragma unroll
        for (int c = 0; c < 8; ++c) acc[r][c] = 0.f;

    for (int k0 = 0; k0 < HD; k0 += 16) {
        const float* xrow = X + (size_t)(bm + am) * HD + k0 + ak;
        float4 a0 = *(const float4*)(xrow);
        float4 a1 = *(const float4*)(xrow + 4);
        As[ak + 0][am] = a0.x; As[ak + 1][am] = a0.y;
        As[ak + 2][am] = a0.z; As[ak + 3][am] = a0.w;
        As[ak + 4][am] = a1.x; As[ak + 5][am] = a1.y;
        As[ak + 6][am] = a1.z; As[ak + 7][am] = a1.w;
        {
            int k = k0 + bk;
            float4 b0, b1;
            if (k < 256) {
                const float* src = (jhi ? wi : wr) + (size_t)k * 256 + jj;
                b0 = *(const float4*)(src);
                b1 = *(const float4*)(src + 4);
            } else {
                const float* src = (jhi ? wr : wi) + (size_t)(k - 256) * 256 + jj;
                b0 = *(const float4*)(src);
                b1 = *(const float4*)(src + 4);
                if (!jhi) {
                    b0.x = -b0.x; b0.y = -b0.y; b0.z = -b0.z; b0.w = -b0.w;
                    b1.x = -b1.x; b1.y = -b1.y; b1.z = -b1.z; b1.w = -b1.w;
                }
            }
            *(float4*)&Bs[bk][bj]     = b0;
            *(float4*)&Bs[bk][bj + 4] = b1;
        }
        __syncthreads();

#pragma unroll
        for (int kk = 0; kk < 16; ++kk) {
            float4 av0 = *(const float4*)&As[kk][ty * 8];
            float4 av1 = *(const float4*)&As[kk][ty * 8 + 4];
            float4 bv0 = *(const float4*)&Bs[kk][tx * 8];
            float4 bv1 = *(const float4*)&Bs[kk][tx * 8 + 4];
            float a[8] = {av0.x, av0.y, av0.z, av0.w, av1.x, av1.y, av1.z, av1.w};
            float b[8] = {bv0.x, bv0.y, bv0.z, bv0.w, bv1.x, bv1.y, bv1.z, bv1.w};
#pragma unroll
            for (int r = 0; r < 8; ++r)
#pragma unroll
                for (int c = 0; c < 8; ++c)
                    acc[r][c] = fmaf(a[r], b[c], acc[r][c]);
        }
        __syncthreads();
    }

    const int col0 = bn + tx * 8;
    float bias[8];
#pragma unroll
    for (int c = 0; c < 8; ++c) {
        int j = col0 + c;
        bias[c] = (j < 256) ? br[j] : bi[j - 256];
    }
#pragma unroll
    for (int r = 0; r < 8; ++r) {
        float* yrow = Y + (size_t)(bm + ty * 8 + r) * HD + col0;
        float4 v0 = make_float4(acc[r][0] + bias[0], acc[r][1] + bias[1],
                                acc[r][2] + bias[2], acc[r][3] + bias[3]);
        float4 v1 = make_float4(acc[r][4] + bias[4], acc[r][5] + bias[5],
                                acc[r][6] + bias[6], acc[r][7] + bias[7]);
        *(float4*)(yrow)     = v0;
        *(float4*)(yrow + 4) = v1;
    }
}

// ---------------------------------------------------------------------------
// Fused pipelined kernel: 144 CTAs (single wave, all resident).
//   clusters 0-7  : layer-0 scan (batch=cl), publishes chunk flags
//   clusters 8-15 : layer-1 scan (batch=cl-8), gates on wx1 chunk flags
//   CTAs 128-143  : 16 persistent GEMM CTAs computing wx1 chunk-by-chunk
// ---------------------------------------------------------------------------
struct SmemScan {
    float hbuf[2][HD];
    float stage[64];
    unsigned long long mbar[2];
};
struct SmemGemm {
    float As[16][132];
    float Bs[16][132];
};
union SmemU {
    SmemScan s;
    SmemGemm g;
};

static __device__ void scan_body(
    SmemScan& sm,
    const float* wx, const float* ur, const float* ui,
    const float* ubr, const float* ubi,
    float* out, int b, bool publish, bool gate, unsigned* flags)
{
    unsigned rank;
    asm("mov.u32 %0, %%cluster_ctarank;" : "=r"(rank));
    const int tid  = threadIdx.x;
    const int lane = tid & 31;
    const int jg   = tid >> 4;
    const int kg   = tid & 15;
    const int j0   = (int)rank * 64 + jg * 4;
    const int jj   = j0 & 255;
    const bool jhi = j0 >= 256;

    const unsigned hb_u32 = su32(&sm.hbuf[0][0]);
    const unsigned st_u32 = su32(&sm.stage[0]);
    const unsigned mb_u32 = su32(&sm.mbar[0]);

    if (tid == 0) {
        asm volatile("mbarrier.init.shared.b64 [%0], %1;" :: "r"(mb_u32),     "r"(1u) : "memory");
        asm volatile("mbarrier.init.shared.b64 [%0], %1;" :: "r"(mb_u32 + 8), "r"(1u) : "memory");
        asm volatile("mbarrier.arrive.expect_tx.shared::cta.b64 _, [%0], %1;"
                     :: "r"(mb_u32),     "r"(2048u) : "memory");
        asm volatile("mbarrier.arrive.expect_tx.shared::cta.b64 _, [%0], %1;"
                     :: "r"(mb_u32 + 8), "r"(2048u) : "memory");
    }
    __syncthreads();
    asm volatile("barrier.cluster.arrive.aligned;" ::: "memory");
    asm volatile("barrier.cluster.wait.aligned;"   ::: "memory");

    unsigned dsth[8], dstm[8];
#pragma unroll
    for (int d = 0; d < 8; ++d) {
        asm("mapa.shared::cluster.u32 %0, %1, %2;" : "=r"(dsth[d]) : "r"(hb_u32), "r"(d));
        asm("mapa.shared::cluster.u32 %0, %1, %2;" : "=r"(dstm[d]) : "r"(mb_u32), "r"(d));
    }
    const unsigned my_off = (unsigned)(rank * 256);

    // ---- weight slice into registers, packed f32x2 along k ----
    unsigned long long w2[4][16];
#pragma unroll
    for (int q = 0; q < 8; ++q) {
        const int k = q * 64 + kg * 4;
        float4 r0, r1, r2, r3;
        if (k < 256) {
            const float* src = (jhi ? ui : ur) + (size_t)k * 256 + jj;
            r0 = *(const float4*)(src);
            r1 = *(const float4*)(src + 256);
            r2 = *(const float4*)(src + 512);
            r3 = *(const float4*)(src + 768);
        } else {
            const float* src = (jhi ? ur : ui) + (size_t)(k - 256) * 256 + jj;
            const float s = jhi ? 1.f : -1.f;
            r0 = *(const float4*)(src);
            r1 = *(const float4*)(src + 256);
            r2 = *(const float4*)(src + 512);
            r3 = *(const float4*)(src + 768);
            r0.x *= s; r0.y *= s; r0.z *= s; r0.w *= s;
            r1.x *= s; r1.y *= s; r1.z *= s; r1.w *= s;
            r2.x *= s; r2.y *= s; r2.z *= s; r2.w *= s;
            r3.x *= s; r3.y *= s; r3.z *= s; r3.w *= s;
        }
        w2[0][2*q]   = packf2(r0.x, r1.x);
        w2[1][2*q]   = packf2(r0.y, r1.y);
        w2[2][2*q]   = packf2(r0.z, r1.z);
        w2[3][2*q]   = packf2(r0.w, r1.w);
        w2[0][2*q+1] = packf2(r2.x, r3.x);
        w2[1][2*q+1] = packf2(r2.y, r3.y);
        w2[2][2*q+1] = packf2(r2.z, r3.z);
        w2[3][2*q+1] = packf2(r2.w, r3.w);
    }
    const float4 ub = jhi ? *(const float4*)(ubi + jj)
                          : *(const float4*)(ubr + jj);

    const float* wx_b  = wx  + (size_t)b * (T_LEN * HD);
    float*       out_b = out + (size_t)b * (T_LEN * HD);
    unsigned* wx_ready = flags + 64 + b * NCHUNK;   // layer-1 gate flags
    unsigned* my_flag  = flags + b * 8 + rank;      // layer-0 publish flag

    // ---- gate chunk 0 (layer 1 only) ----
    if (gate) {
        if (tid == 0) {
            while (ld_acq(wx_ready) == 0) __nanosleep(128);
        }
        __syncthreads();
    }

    // ---- t = 0 (h_prev = 0) ----
    {
        float4 wv = __ldcg((const float4*)(wx_b + j0));
        float4 yv;
        yv.x = fast_tanh(wv.x + ub.x);
        yv.y = fast_tanh(wv.y + ub.y);
        yv.z = fast_tanh(wv.z + ub.z);
        yv.w = fast_tanh(wv.w + ub.w);
        if ((lane & 15) == 0) *(float4*)&sm.stage[jg * 4] = yv;
        if ((lane & 15) == 8) *(float4*)(out_b + j0) = yv;
        __syncthreads();
        if (tid == 0) {
            asm volatile("fence.proxy.async.shared::cta;" ::: "memory");
#pragma unroll
            for (int d = 0; d < 8; ++d) {
                asm volatile(
                    "cp.async.bulk.shared::cluster.shared::cta.mbarrier::complete_tx::bytes "
                    "[%0], [%1], %2, [%3];"
                    :: "r"(dsth[d] + my_off), "r"(st_u32), "r"(256u), "r"(dstm[d])
                    : "memory");
            }
        }
    }

    for (int t = 1; t < T_LEN; ++t) {
        // chunk gate (layer 1): once every 128 steps
        if (gate && (t & (CHUNK - 1)) == 0) {
            if (tid == 0) {
                const unsigned c = (unsigned)(t >> 7);
                while (ld_acq(wx_ready + c) == 0) __nanosleep(128);
            }
            __syncthreads();
        }

        float4 wv = __ldcg((const float4*)(wx_b + (size_t)t * HD + j0));

        const int use  = t - 1;
        const int rbuf = use & 1;
        mbar_wait(mb_u32 + rbuf * 8, (unsigned)((use >> 1) & 1));

        if (tid == 0) {
            asm volatile("mbarrier.arrive.expect_tx.shared::cta.b64 _, [%0], %1;"
                         :: "r"(mb_u32 + rbuf * 8), "r"(2048u) : "memory");
        }

        unsigned long long h2[16];
        const float* hp = &sm.hbuf[rbuf][0];
#pragma unroll
        for (int q = 0; q < 8; ++q) {
            ulonglong2 v = *(const ulonglong2*)(hp + q * 64 + kg * 4);
            h2[2*q]   = v.x;
            h2[2*q+1] = v.y;
        }

        unsigned long long acc0 = 0, acc1 = 0, acc2 = 0, acc3 = 0;
#pragma unroll
        for (int q = 0; q < 16; ++q) {
            asm("fma.rn.f32x2 %0, %1, %2, %0;" : "+l"(acc0) : "l"(h2[q]), "l"(w2[0][q]));
            asm("fma.rn.f32x2 %0, %1, %2, %0;" : "+l"(acc1) : "l"(h2[q]), "l"(w2[1][q]));
            asm("fma.rn.f32x2 %0, %1, %2, %0;" : "+l"(acc2) : "l"(h2[q]), "l"(w2[2][q]));
            asm("fma.rn.f32x2 %0, %1, %2, %0;" : "+l"(acc3) : "l"(h2[q]), "l"(w2[3][q]));
        }
        float a0, a1, a2, a3, hq;
        unpackf2(acc0, a0, hq); a0 += hq;
        unpackf2(acc1, a1, hq); a1 += hq;
        unpackf2(acc2, a2, hq); a2 += hq;
        unpackf2(acc3, a3, hq); a3 += hq;
#pragma unroll
        for (int off = 1; off < 16; off <<= 1) {
            a0 += __shfl_xor_sync(0xffffffffu, a0, off);
            a1 += __shfl_xor_sync(0xffffffffu, a1, off);
            a2 += __shfl_xor_sync(0xffffffffu, a2, off);
            a3 += __shfl_xor_sync(0xffffffffu, a3, off);
        }

        float4 yv;
        yv.x = fast_tanh(wv.x + ub.x + a0);
        yv.y = fast_tanh(wv.y + ub.y + a1);
        yv.z = fast_tanh(wv.z + ub.z + a2);
        yv.w = fast_tanh(wv.w + ub.w + a3);

        if ((lane & 15) == 0) *(float4*)&sm.stage[jg * 4] = yv;
        if ((lane & 15) == 8) *(float4*)(out_b + (size_t)t * HD + j0) = yv;

        if (t < T_LEN - 1) {
            __syncthreads();
            if (tid == 0) {
                const unsigned boff = (unsigned)((t & 1) * 2048) + my_off;
                const unsigned moff = (unsigned)((t & 1) * 8);
                asm volatile("fence.proxy.async.shared::cta;" ::: "memory");
#pragma unroll
                for (int d = 0; d < 8; ++d) {
                    asm volatile(
                        "cp.async.bulk.shared::cluster.shared::cta.mbarrier::complete_tx::bytes "
                        "[%0], [%1], %2, [%3];"
                        :: "r"(dsth[d] + boff), "r"(st_u32), "r"(256u), "r"(dstm[d] + moff)
                        : "memory");
                }
                // publish layer-0 chunk progress (stores ordered by the
                // __syncthreads above + release)
                if (publish && (t & (CHUNK - 1)) == (CHUNK - 1)) {
                    st_rel(my_flag, (unsigned)((t >> 7) + 1));
                }
            }
        }
    }

    if (publish) {
        __syncthreads();
        if (tid == 0) st_rel(my_flag, (unsigned)NCHUNK);  // final chunk
    }

    asm volatile("barrier.cluster.arrive.aligned;" ::: "memory");
    asm volatile("barrier.cluster.wait.aligned;"   ::: "memory");
}

// GEMM body: wx1[rows of (b,c)] = h0 @ Mw1 + bias, tile 128x128, 4 col tiles.
static __device__ void gemm_body(
    SmemGemm& sg, int g,
    const float* X, const float* wr, const float* wi,
    const float* br, const float* bi, float* Y, unsigned* flags)
{
    const int tid = threadIdx.x;
    const int tx  = tid & 15;
    const int ty  = tid >> 4;
    const int am  = tid >> 1;
    const int ak  = (tid & 1) * 8;
    const int bk  = tid >> 4;
    const int bj  = (tid & 15) * 8;

    for (int pair = g; pair < BATCH * NCHUNK; pair += 16) {
        const int c = pair >> 3;
        const int b = pair & 7;

        // wait for layer-0 chunk c of batch b (all 8 rank flags >= c+1)
        if (tid < 8) {
            const unsigned* f = flags + b * 8 + tid;
            while (ld_acq(f) < (unsigned)(c + 1)) __nanosleep(256);
        }
        __syncthreads();

        const int bm = b * T_LEN + c * CHUNK;

        for (int bnb = 0; bnb < 4; ++bnb) {
            const int bn = bnb * 128;
            const bool jhi = (bn + bj) >= 256;
            const int  jj  = (bn + bj) & 255;

            float acc[8][8];
#pragma unroll
            for (int r = 0; r < 8; ++r)
#pragma unroll
                for (int cc = 0; cc < 8; ++cc) acc[r][cc] = 0.f;

            for (int k0 = 0; k0 < HD; k0 += 16) {
                const float* xrow = X + (size_t)(bm + am) * HD + k0 + ak;
                float4 a0 = __ldcg((const float4*)(xrow));
                float4 a1 = __ldcg((const float4*)(xrow + 4));
                sg.As[ak + 0][am] = a0.x; sg.As[ak + 1][am] = a0.y;
                sg.As[ak + 2][am] = a0.z; sg.As[ak + 3][am] = a0.w;
                sg.As[ak + 4][am] = a1.x; sg.As[ak + 5][am] = a1.y;
                sg.As[ak + 6][am] = a1.z; sg.As[ak + 7][am] = a1.w;
                {
                    int k = k0 + bk;
                    float4 b0, b1;
                    if (k < 256) {
                        const float* src = (jhi ? wi : wr) + (size_t)k * 256 + jj;
                        b0 = *(const float4*)(src);
                        b1 = *(const float4*)(src + 4);
                    } else {
                        const float* src = (jhi ? wr : wi) + (size_t)(k - 256) * 256 + jj;
                        b0 = *(const float4*)(src);
                        b1 = *(const float4*)(src + 4);
                        if (!jhi) {
                            b0.x = -b0.x; b0.y = -b0.y; b0.z = -b0.z; b0.w = -b0.w;
                            b1.x = -b1.x; b1.y = -b1.y; b1.z = -b1.z; b1.w = -b1.w;
                        }
                    }
                    *(float4*)&sg.Bs[bk][bj]     = b0;
                    *(float4*)&sg.Bs[bk][bj + 4] = b1;
                }
                __syncthreads();

#pragma unroll
                for (int kk = 0; kk < 16; ++kk) {
                    float4 av0 = *(const float4*)&sg.As[kk][ty * 8];
                    float4 av1 = *(const float4*)&sg.As[kk][ty * 8 + 4];
                    float4 bv0 = *(const float4*)&sg.Bs[kk][tx * 8];
                    float4 bv1 = *(const float4*)&sg.Bs[kk][tx * 8 + 4];
                    float a[8] = {av0.x, av0.y, av0.z, av0.w, av1.x, av1.y, av1.z, av1.w};
                    float bb[8] = {bv0.x, bv0.y, bv0.z, bv0.w, bv1.x, bv1.y, bv1.z, bv1.w};
#pragma unroll
                    for (int r = 0; r < 8; ++r)
#pragma unroll
                        for (int cc = 0; cc < 8; ++cc)
                            acc[r][cc] = fmaf(a[r], bb[cc], acc[r][cc]);
                }
                __syncthreads();
            }

            const int col0 = bn + tx * 8;
            float bias[8];
#pragma unroll
            for (int cc = 0; cc < 8; ++cc) {
                int j = col0 + cc;
                bias[cc] = (j < 256) ? br[j] : bi[j - 256];
            }
#pragma unroll
            for (int r = 0; r < 8; ++r) {
                float* yrow = Y + (size_t)(bm + ty * 8 + r) * HD + col0;
                float4 v0 = make_float4(acc[r][0] + bias[0], acc[r][1] + bias[1],
                                        acc[r][2] + bias[2], acc[r][3] + bias[3]);
                float4 v1 = make_float4(acc[r][4] + bias[4], acc[r][5] + bias[5],
                                        acc[r][6] + bias[6], acc[r][7] + bias[7]);
                *(float4*)(yrow)     = v0;
                *(float4*)(yrow + 4) = v1;
            }
        }

        __syncthreads();
        if (tid == 0) st_rel(flags + 64 + b * NCHUNK + c, 1u);
    }
}

__global__ void __cluster_dims__(8, 1, 1) __launch_bounds__(256, 1)
fused_kernel(const float* __restrict__ wx0,
             const float* __restrict__ l0_ur, const float* __restrict__ l0_ui,
             const float* __restrict__ l0_ubr, const float* __restrict__ l0_ubi,
             const float* __restrict__ l1_wr, const float* __restrict__ l1_wi,
             const float* __restrict__ l1_wbr, const float* __restrict__ l1_wbi,
             const float* __restrict__ l1_ur, const float* __restrict__ l1_ui,
             const float* __restrict__ l1_ubr, const float* __restrict__ l1_ubi,
             float* h0, float* wx1, float* out, unsigned* flags)
{
    __shared__ __align__(16) SmemU smem;
    const int cl = blockIdx.x >> 3;
    if (cl < 8) {
        scan_body(smem.s, wx0, l0_ur, l0_ui, l0_ubr, l0_ubi,
                  h0, cl, /*publish=*/true, /*gate=*/false, flags);
    } else if (cl < 16) {
        scan_body(smem.s, wx1, l1_ur, l1_ui, l1_ubr, l1_ubi,
                  out, cl - 8, /*publish=*/false, /*gate=*/true, flags);
    } else {
        gemm_body(smem.g, blockIdx.x - 128,
                  h0, l1_wr, l1_wi, l1_wbr, l1_wbi, wx1, flags);
    }
}

// ---------------------------------------------------------------------------
extern "C" void kernel_launch(void* const* d_in, const int* in_sizes, int n_in,
                              void* d_out, int out_size)
{
    const float* x      = (const float*)d_in[0];
    const float* l0_wr  = (const float*)d_in[1];
    const float* l0_wi  = (const float*)d_in[2];
    const float* l0_wbr = (const float*)d_in[3];
    const float* l0_wbi = (const float*)d_in[4];
    const float* l0_ur  = (const float*)d_in[5];
    const float* l0_ui  = (const float*)d_in[6];
    const float* l0_ubr = (const float*)d_in[7];
    const float* l0_ubi = (const float*)d_in[8];
    const float* l1_wr  = (const float*)d_in[9];
    const float* l1_wi  = (const float*)d_in[10];
    const float* l1_wbr = (const float*)d_in[11];
    const float* l1_wbi = (const float*)d_in[12];
    const float* l1_ur  = (const float*)d_in[13];
    const float* l1_ui  = (const float*)d_in[14];
    const float* l1_ubr = (const float*)d_in[15];
    const float* l1_ubi = (const float*)d_in[16];

    float* out = (float*)d_out;

    void *p_wx0_v = nullptr, *p_h0_v = nullptr, *p_wx1_v = nullptr, *p_fl_v = nullptr;
    cudaGetSymbolAddress(&p_wx0_v, g_wx0);
    cudaGetSymbolAddress(&p_h0_v,  g_h0);
    cudaGetSymbolAddress(&p_wx1_v, g_wx1);
    cudaGetSymbolAddress(&p_fl_v,  g_flags);
    float* p_wx0 = (float*)p_wx0_v;
    float* p_h0  = (float*)p_h0_v;
    float* p_wx1 = (float*)p_wx1_v;
    unsigned* p_fl = (unsigned*)p_fl_v;

    // reset pipeline flags (graph-replay safe)
    cudaMemsetAsync(p_fl, 0, sizeof(unsigned) * (64 + BATCH * NCHUNK));

    dim3 pgrid(NROWS / 128, HD / 128);
    proj_kernel<<<pgrid, 256>>>(x, l0_wr, l0_wi, l0_wbr, l0_wbi, p_wx0);

    fused_kernel<<<144, 256>>>(p_wx0,
                               l0_ur, l0_ui, l0_ubr, l0_ubi,
                               l1_wr, l1_wi, l1_wbr, l1_wbi,
                               l1_ur, l1_ui, l1_ubr, l1_ubi,
                               p_h0, p_wx1, out, p_fl);
}